// round 14
// baseline (speedup 1.0000x reference)
#include <cuda_runtime.h>
#include <cuda_fp16.h>
#include <mma.h>

using namespace nvcuda;

#define BB   32
#define TT   512
#define HHD  512
#define KVD  1024
#define OUTD 128
#define XKD  1152   // OUT + KV
#define SDEC 128

// ---------------- static scratch ----------------
__device__ __half g_key[BB*TT*KVD];           // 33.5 MB (fp16)
__device__ __half g_val[BB*TT*KVD];           // 33.5 MB (fp16)
__device__ alignas(16) __half g_wih0h[2048*XKD];
__device__ alignas(16) __half g_whh0h[2048*HHD];
__device__ alignas(16) __half g_wih1h[2048*HHD];
__device__ alignas(16) __half g_whh1h[2048*HHD];
__device__ alignas(16) __half g_wqh[KVD*HHD];
__device__ float g_q[BB*KVD];
__device__ float g_scores[BB*TT];
__device__ float g_xT[(XKD/4)*BB*4];          // x=[y,ctx] grouped-4 transposed
__device__ float g_h0T[2][(HHD/4)*BB*4];      // ping-pong
__device__ float g_h1T[2][(HHD/4)*BB*4];
__device__ float g_c0[HHD*BB];                // [u][b]
__device__ float g_c1[HHD*BB];

__device__ __forceinline__ float fast_tanh(float x) {      // accurate (LSTM cells)
    float e = __expf(2.0f * x);
    return 1.0f - __fdividef(2.0f, e + 1.0f);
}
__device__ __forceinline__ float tanha(float x) {          // HW MUFU (scores)
    float y; asm("tanh.approx.f32 %0, %1;" : "=f"(y) : "f"(x)); return y;
}
__device__ __forceinline__ float sigm(float x) {
    return __fdividef(1.0f, 1.0f + __expf(-x));
}
__device__ __forceinline__ float dot4(float4 a, float4 b) {
    return a.x*b.x + a.y*b.y + a.z*b.z + a.w*b.w;
}
// dot of 4 halves (packed in uint2) with float4
__device__ __forceinline__ float dot4h(uint2 wv, float4 x) {
    __half2* hp = (__half2*)&wv;
    float2 a = __half22float2(hp[0]);
    float2 b = __half22float2(hp[1]);
    return a.x * x.x + a.y * x.y + b.x * x.z + b.y * x.w;
}
// grouped-4 transposed float index for (k, batch m)
__device__ __forceinline__ int idx4(int k, int m) { return ((k >> 2) << 7) + (m << 2) + (k & 3); }

// ---------------------------------------------------------------
// convert weights to fp16 (one-time): 16384 floats per block
// ---------------------------------------------------------------
__global__ void __launch_bounds__(256) convertw_kernel(const float* __restrict__ wih0,
                                                       const float* __restrict__ whh0,
                                                       const float* __restrict__ wih1,
                                                       const float* __restrict__ whh1,
                                                       const float* __restrict__ Wq) {
    int bx = blockIdx.x;
    const float* src; __half* dst; size_t off;
    if (bx < 144)      { src = wih0; dst = g_wih0h; off = (size_t)bx * 16384; }
    else if (bx < 208) { src = whh0; dst = g_whh0h; off = (size_t)(bx - 144) * 16384; }
    else if (bx < 272) { src = wih1; dst = g_wih1h; off = (size_t)(bx - 208) * 16384; }
    else if (bx < 336) { src = whh1; dst = g_whh1h; off = (size_t)(bx - 272) * 16384; }
    else               { src = Wq;   dst = g_wqh;   off = (size_t)(bx - 336) * 16384; }
    const float4* s4 = (const float4*)(src + off);
    for (int i = threadIdx.x; i < 4096; i += 256) {
        float4 v = __ldg(s4 + i);
        union { __half h[4]; uint2 u; } pk;
        pk.h[0] = __float2half_rn(v.x); pk.h[1] = __float2half_rn(v.y);
        pk.h[2] = __float2half_rn(v.z); pk.h[3] = __float2half_rn(v.w);
        *(uint2*)(dst + off + (size_t)i * 4) = pk.u;
    }
}

// ---------------------------------------------------------------
// init: blocks 0..31 -> q0 = h0[0] @ Wq^T ; blocks 32..39 -> state transpose + y0=0
// ---------------------------------------------------------------
__global__ void init_kernel(const float* __restrict__ h0, const float* __restrict__ c0,
                            const float* __restrict__ Wq) {
    int bx = blockIdx.x, tid = threadIdx.x;
    if (bx < 32) {
        __shared__ float sh[512];
        for (int p = tid; p < 512; p += 256) sh[p] = h0[bx * 512 + p];
        __syncthreads();
        int w = tid >> 5, lane = tid & 31;
        const float4* shv = (const float4*)sh;
        for (int jj = 0; jj < 128; jj++) {
            int j = (w << 7) + jj;
            const float4* wq = (const float4*)(Wq + (size_t)j * 512);
            float acc = 0.f;
#pragma unroll
            for (int i = 0; i < 4; i++)
                acc += dot4(__ldg(&wq[lane + (i << 5)]), shv[lane + (i << 5)]);
#pragma unroll
            for (int off = 16; off; off >>= 1) acc += __shfl_xor_sync(0xffffffffu, acc, off);
            if (lane == 0) g_q[(bx << 10) + j] = acc;
        }
    } else {
        int p0 = (bx - 32) * 256 + tid;
        for (int i = p0; i < BB * HHD; i += 8 * 256) {
            int b = i >> 9, u = i & 511;
            int ix = idx4(u, b);
            g_h0T[0][ix] = h0[i];
            g_h1T[0][ix] = h0[BB * HHD + i];
            g_c0[u * 32 + b] = c0[i];
            g_c1[u * 32 + b] = c0[BB * HHD + i];
        }
        for (int i = p0; i < OUTD * 32; i += 8 * 256) g_xT[i] = 0.f;
    }
}

// ---------------------------------------------------------------
// key/value precompute via WMMA, double-buffered software pipeline
// ---------------------------------------------------------------
__global__ void __launch_bounds__(256) gemm_kv_kernel(const float* __restrict__ A,
                                                      const float* __restrict__ Wk,
                                                      const float* __restrict__ Wv) {
    const float* W = blockIdx.z ? Wv : Wk;
    __half* C = blockIdx.z ? g_val : g_key;
    int m0 = blockIdx.y << 7, n0 = blockIdx.x << 7;
    __shared__ alignas(256) __half As[2][128][40];
    __shared__ alignas(256) __half Bs[2][128][40];
    __shared__ alignas(256) float stage[8][256];
    int tid = threadIdx.x, lane = tid & 31, wid = tid >> 5;
    int wm = (wid & 3) << 5;
    int wn = (wid >> 2) << 6;

    wmma::fragment<wmma::accumulator, 16, 16, 16, float> acc[2][4];
#pragma unroll
    for (int mf = 0; mf < 2; mf++)
#pragma unroll
        for (int nf = 0; nf < 4; nf++) wmma::fill_fragment(acc[mf][nf], 0.0f);

    int r = tid & 127;
    const float* srcrow = (tid < 128) ? (A + (size_t)(m0 + r) * 1024)
                                      : (W + (size_t)(n0 + r) * 1024);

    float4 f[8];
#define GEMM_LOAD(k0)                                                   \
    {                                                                   \
        _Pragma("unroll")                                               \
        for (int j = 0; j < 4; j++) {                                   \
            f[2*j]   = __ldg((const float4*)(srcrow + (k0) + j * 8));   \
            f[2*j+1] = __ldg((const float4*)(srcrow + (k0) + j * 8 + 4));\
        }                                                               \
    }
#define GEMM_STORE(buf)                                                 \
    {                                                                   \
        __half* dstrow = (tid < 128) ? &As[buf][r][0] : &Bs[buf][r][0]; \
        _Pragma("unroll")                                               \
        for (int j = 0; j < 4; j++) {                                   \
            union { __half h[8]; uint4 u; } pk;                         \
            pk.h[0] = __float2half_rn(f[2*j].x);                        \
            pk.h[1] = __float2half_rn(f[2*j].y);                        \
            pk.h[2] = __float2half_rn(f[2*j].z);                        \
            pk.h[3] = __float2half_rn(f[2*j].w);                        \
            pk.h[4] = __float2half_rn(f[2*j+1].x);                      \
            pk.h[5] = __float2half_rn(f[2*j+1].y);                      \
            pk.h[6] = __float2half_rn(f[2*j+1].z);                      \
            pk.h[7] = __float2half_rn(f[2*j+1].w);                      \
            *(uint4*)(dstrow + j * 8) = pk.u;                           \
        }                                                               \
    }

    GEMM_LOAD(0);
    GEMM_STORE(0);
    __syncthreads();

    for (int c = 0; c < 32; c++) {
        if (c < 31) GEMM_LOAD((c + 1) << 5);
        int buf = c & 1;
#pragma unroll
        for (int ks = 0; ks < 32; ks += 16) {
            wmma::fragment<wmma::matrix_a, 16, 16, 16, __half, wmma::row_major> af[2];
            wmma::fragment<wmma::matrix_b, 16, 16, 16, __half, wmma::col_major> bf[4];
#pragma unroll
            for (int mf = 0; mf < 2; mf++)
                wmma::load_matrix_sync(af[mf], &As[buf][wm + (mf << 4)][ks], 40);
#pragma unroll
            for (int nf = 0; nf < 4; nf++)
                wmma::load_matrix_sync(bf[nf], &Bs[buf][wn + (nf << 4)][ks], 40);
#pragma unroll
            for (int mf = 0; mf < 2; mf++)
#pragma unroll
                for (int nf = 0; nf < 4; nf++)
                    wmma::mma_sync(acc[mf][nf], af[mf], bf[nf], acc[mf][nf]);
        }
        if (c < 31) GEMM_STORE((c + 1) & 1);
        __syncthreads();
    }
#undef GEMM_LOAD
#undef GEMM_STORE

#pragma unroll
    for (int mf = 0; mf < 2; mf++)
#pragma unroll
        for (int nf = 0; nf < 4; nf++) {
            wmma::store_matrix_sync(stage[wid], acc[mf][nf], 16, wmma::mem_row_major);
            __syncwarp();
#pragma unroll
            for (int i = lane; i < 128; i += 32) {
                int rr = i >> 3, c2 = (i & 7) << 1;
                __half2 h = __floats2half2_rn(stage[wid][rr * 16 + c2],
                                              stage[wid][rr * 16 + c2 + 1]);
                *(__half2*)(C + (size_t)(m0 + wm + (mf << 4) + rr) * 1024
                              + n0 + wn + (nf << 4) + c2) = h;
            }
            __syncwarp();
        }
}

// ---------------------------------------------------------------
// scores body (R12 version): 256 threads; (chunk, b) = 32-t slab; warp 4 rows
// ---------------------------------------------------------------
__device__ __forceinline__ void scores_body(const float* __restrict__ We,
                                            int chunk, int b, int tid,
                                            float* sq, float* swe) {
    for (int p = tid; p < 1024; p += 256) { sq[p] = g_q[(b << 10) + p]; swe[p] = We[p]; }
    __syncthreads();
    int w = tid >> 5, lane = tid & 31;
    const float4* qv = (const float4*)sq;
    const float4* wv = (const float4*)swe;
#pragma unroll
    for (int r = 0; r < 4; r++) {
        int t = (chunk << 5) + (w << 2) + r;
        const uint4* kp = (const uint4*)(g_key + ((size_t)(b * 512 + t) << 10));
        uint4 kk[4];
#pragma unroll
        for (int i = 0; i < 4; i++) kk[i] = __ldg(&kp[lane + (i << 5)]);
        float acc = 0.f;
#pragma unroll
        for (int i = 0; i < 4; i++) {
            int q4 = (lane + (i << 5)) << 1;
            float4 qa = qv[q4],     qb = qv[q4 + 1];
            float4 wa = wv[q4],     wb = wv[q4 + 1];
            const __half2* hp = (const __half2*)&kk[i];
            float2 f0 = __half22float2(hp[0]);
            float2 f1 = __half22float2(hp[1]);
            float2 f2 = __half22float2(hp[2]);
            float2 f3 = __half22float2(hp[3]);
            acc += wa.x * tanha(qa.x + f0.x);
            acc += wa.y * tanha(qa.y + f0.y);
            acc += wa.z * tanha(qa.z + f1.x);
            acc += wa.w * tanha(qa.w + f1.y);
            acc += wb.x * tanha(qb.x + f2.x);
            acc += wb.y * tanha(qb.y + f2.y);
            acc += wb.z * tanha(qb.z + f3.x);
            acc += wb.w * tanha(qb.w + f3.y);
        }
#pragma unroll
        for (int off = 16; off; off >>= 1) acc += __shfl_xor_sync(0xffffffffu, acc, off);
        if (lane == 0) g_scores[(b << 9) + t] = acc;
    }
}

__global__ void __launch_bounds__(256) scores_kernel(const float* __restrict__ We) {
    __shared__ float sq[1024], swe[1024];
    scores_body(We, blockIdx.x, blockIdx.y, threadIdx.x, sq, swe);
}

// ---------------------------------------------------------------
// softmax + context (R12 version): grid (8,32), 1024 threads, 64 t-phases
// ---------------------------------------------------------------
__global__ void __launch_bounds__(1024) ctx_kernel() {
    int b = blockIdx.y, tid = threadIdx.x;
    int lane = tid & 31, wid = tid >> 5;
    __shared__ float sal[512];
    __shared__ float racc[64 * 128];
    __shared__ float part2[1024];
    __shared__ float wm[32], ws[32];

    float v = (tid < 512) ? g_scores[(b << 9) + tid] : -1e30f;
    float m = v;
#pragma unroll
    for (int o = 16; o; o >>= 1) m = fmaxf(m, __shfl_xor_sync(0xffffffffu, m, o));
    if (lane == 0) wm[wid] = m;
    __syncthreads();
    if (tid < 32) {
        float x = wm[tid];
#pragma unroll
        for (int o = 16; o; o >>= 1) x = fmaxf(x, __shfl_xor_sync(0xffffffffu, x, o));
        wm[tid] = x;
    }
    __syncthreads();
    float mx = wm[0];
    float e = (tid < 512) ? __expf(v - mx) : 0.f;
    if (tid < 512) sal[tid] = e;
    float s = e;
#pragma unroll
    for (int o = 16; o; o >>= 1) s += __shfl_xor_sync(0xffffffffu, s, o);
    if (lane == 0) ws[wid] = s;
    __syncthreads();
    if (tid < 32) {
        float x = ws[tid];
#pragma unroll
        for (int o = 16; o; o >>= 1) x += __shfl_xor_sync(0xffffffffu, x, o);
        ws[tid] = x;
    }
    __syncthreads();
    float inv = __fdividef(1.0f, ws[0]);

    int tph = (wid << 1) + (lane >> 4);
    int dl  = lane & 15;
    const uint4* vp = (const uint4*)g_val + ((size_t)b << 16) + (blockIdx.x << 4) + dl;
    float a0=0,a1=0,a2=0,a3=0,a4=0,a5=0,a6=0,a7=0;
#pragma unroll
    for (int t = tph; t < 512; t += 64) {
        uint4 vv = __ldg(vp + ((size_t)t << 7));
        float sc = sal[t];
        const __half2* hp = (const __half2*)&vv;
        float2 f0 = __half22float2(hp[0]);
        float2 f1 = __half22float2(hp[1]);
        float2 f2 = __half22float2(hp[2]);
        float2 f3 = __half22float2(hp[3]);
        a0 += sc * f0.x; a1 += sc * f0.y; a2 += sc * f1.x; a3 += sc * f1.y;
        a4 += sc * f2.x; a5 += sc * f2.y; a6 += sc * f3.x; a7 += sc * f3.y;
    }
    float4* r4 = (float4*)racc;
    int base4 = (tph << 5) + (dl << 1);
    r4[base4]     = make_float4(a0, a1, a2, a3);
    r4[base4 + 1] = make_float4(a4, a5, a6, a7);
    __syncthreads();

    {
        int d = tid & 127, g = tid >> 7;
        float sum = 0.f;
#pragma unroll
        for (int i = 0; i < 8; i++) sum += racc[((g + (i << 3)) << 7) + d];
        part2[(g << 7) + d] = sum;
    }
    __syncthreads();
    if (tid < 128) {
        float sum = 0.f;
#pragma unroll
        for (int g = 0; g < 8; g++) sum += part2[(g << 7) + tid];
        int k = 128 + (blockIdx.x << 7) + tid;
        g_xT[((k >> 2) << 7) + (b << 2) + (k & 3)] = sum * inv;
    }
}

// ---------------------------------------------------------------
// lstm0: grid 128 (4 units/block), 512 threads = 16 warps (unit x 4-way k-split)
// Activation slices are shared across the 4 unit-warps -> L1 hits, 4x less L2.
// ---------------------------------------------------------------
__global__ void __launch_bounds__(512) lstm0_kernel(const float* __restrict__ bih,
                                                    const float* __restrict__ bhh,
                                                    int p) {
    __shared__ float part[4][4][4][32];   // [uu][gate][ws][lane]
    int tid = threadIdx.x, wid = tid >> 5, lane = tid & 31;
    int uu = wid >> 2, ws = wid & 3;
    int u = (blockIdx.x << 2) + uu;
    const float4* xT4 = (const float4*)g_xT;
    const float4* hT4 = (const float4*)g_h0T[p];
    const uint2* wihv = (const uint2*)g_wih0h;   // 288 uint2 per row
    const uint2* whhv = (const uint2*)g_whh0h;   // 128 uint2 per row
    float acc[4] = {0.f, 0.f, 0.f, 0.f};

    for (int g = ws * 72; g < ws * 72 + 72; g++) {
        float4 xv = xT4[(g << 5) + lane];
#pragma unroll
        for (int gate = 0; gate < 4; gate++)
            acc[gate] += dot4h(__ldg(&wihv[(size_t)(gate * 512 + u) * 288 + g]), xv);
    }
    for (int g = ws * 32; g < ws * 32 + 32; g++) {
        float4 hv = hT4[(g << 5) + lane];
#pragma unroll
        for (int gate = 0; gate < 4; gate++)
            acc[gate] += dot4h(__ldg(&whhv[(size_t)(gate * 512 + u) * 128 + g]), hv);
    }
#pragma unroll
    for (int gate = 0; gate < 4; gate++) part[uu][gate][ws][lane] = acc[gate];
    __syncthreads();
    if (wid < 4) {
        int uf = (blockIdx.x << 2) + wid;
        float gv[4];
#pragma unroll
        for (int gate = 0; gate < 4; gate++) {
            int j = gate * 512 + uf;
            float s = part[wid][gate][0][lane] + part[wid][gate][1][lane] +
                      part[wid][gate][2][lane] + part[wid][gate][3][lane];
            gv[gate] = s + bih[j] + bhh[j];
        }
        float c = g_c0[uf * 32 + lane];
        float cn = sigm(gv[1]) * c + sigm(gv[0]) * fast_tanh(gv[2]);
        float hn = sigm(gv[3]) * fast_tanh(cn);
        g_c0[uf * 32 + lane] = cn;
        g_h0T[1 - p][idx4(uf, lane)] = hn;
    }
}

// ---------------------------------------------------------------
// lstm1 (+ q-projection): blocks<128 lstm (4 units/block, 4-way k-split),
// blocks 128..191 qproj (16 warps, one j per warp)
// ---------------------------------------------------------------
__global__ void __launch_bounds__(512) lstm1q_kernel(const float* __restrict__ bih,
                                                     const float* __restrict__ bhh,
                                                     int p) {
    int tid = threadIdx.x, wid = tid >> 5, lane = tid & 31;
    const float4* h0n = (const float4*)g_h0T[1 - p];
    if (blockIdx.x < 128) {
        __shared__ float part[4][4][4][32];
        int uu = wid >> 2, ws = wid & 3;
        int u = (blockIdx.x << 2) + uu;
        const float4* hT4 = (const float4*)g_h1T[p];
        const uint2* wihv = (const uint2*)g_wih1h;   // 128 uint2 per row
        const uint2* whhv = (const uint2*)g_whh1h;
        float acc[4] = {0.f, 0.f, 0.f, 0.f};
        for (int g = ws * 32; g < ws * 32 + 32; g++) {
            float4 xv = h0n[(g << 5) + lane];
            float4 hv = hT4[(g << 5) + lane];
#pragma unroll
            for (int gate = 0; gate < 4; gate++) {
                int j = gate * 512 + u;
                acc[gate] += dot4h(__ldg(&wihv[(size_t)j * 128 + g]), xv);
                acc[gate] += dot4h(__ldg(&whhv[(size_t)j * 128 + g]), hv);
            }
        }
#pragma unroll
        for (int gate = 0; gate < 4; gate++) part[uu][gate][ws][lane] = acc[gate];
        __syncthreads();
        if (wid < 4) {
            int uf = (blockIdx.x << 2) + wid;
            float gv[4];
#pragma unroll
            for (int gate = 0; gate < 4; gate++) {
                int j = gate * 512 + uf;
                float s = part[wid][gate][0][lane] + part[wid][gate][1][lane] +
                          part[wid][gate][2][lane] + part[wid][gate][3][lane];
                gv[gate] = s + bih[j] + bhh[j];
            }
            float c = g_c1[uf * 32 + lane];
            float cn = sigm(gv[1]) * c + sigm(gv[0]) * fast_tanh(gv[2]);
            float hn = sigm(gv[3]) * fast_tanh(cn);
            g_c1[uf * 32 + lane] = cn;
            g_h1T[1 - p][idx4(uf, lane)] = hn;
        }
    } else {
        // q projection: q = h0n @ Wq^T (fp16 Wq), one warp per output feature j
        int j = (blockIdx.x - 128) * 16 + wid;
        const uint2* wq = (const uint2*)(g_wqh + (size_t)j * 512);
        float acc = 0.f;
        for (int g = 0; g < 128; g++)
            acc += dot4h(__ldg(&wq[g]), h0n[(g << 5) + lane]);
        g_q[lane * 1024 + j] = acc;
    }
}

// ---------------------------------------------------------------
// fused fc (this step) + scores (next step)  (R12 version)
// ---------------------------------------------------------------
__global__ void __launch_bounds__(256) fcscores_kernel(const float* __restrict__ fc_w,
                                                       const float* __restrict__ fc_b,
                                                       const float* __restrict__ We,
                                                       float* __restrict__ out, int s, int p) {
    __shared__ float sq[1024], swe[1024];
    if (blockIdx.x < 16) {
        int w = threadIdx.x >> 5, lane = threadIdx.x & 31;
        int o = blockIdx.x * 8 + w;
        const float4* h1n = (const float4*)g_h1T[1 - p];
        const float4* fw = (const float4*)(fc_w + (size_t)o * 512);
        float acc = 0.f;
        for (int g = 0; g < 128; g++)
            acc += dot4(__ldg(&fw[g]), h1n[(g << 5) + lane]);
        float y = fmaxf(acc + fc_b[o], 0.f);
        out[(size_t)lane * (SDEC * OUTD) + s * OUTD + o] = y;
        g_xT[idx4(o, lane)] = 1.0f + y;
    } else {
        int idx = blockIdx.x - 16;
        scores_body(We, idx & 15, idx >> 4, threadIdx.x, sq, swe);
    }
}

// ---------------------------------------------------------------
extern "C" void kernel_launch(void* const* d_in, const int* in_sizes, int n_in,
                              void* d_out, int out_size) {
    const float* enc  = (const float*)d_in[0];
    const float* h0   = (const float*)d_in[1];
    const float* c0   = (const float*)d_in[2];
    const float* Wk   = (const float*)d_in[3];
    const float* Wq   = (const float*)d_in[4];
    const float* Wv   = (const float*)d_in[5];
    const float* We   = (const float*)d_in[6];
    const float* wih0 = (const float*)d_in[7];
    const float* whh0 = (const float*)d_in[8];
    const float* bih0 = (const float*)d_in[9];
    const float* bhh0 = (const float*)d_in[10];
    const float* wih1 = (const float*)d_in[11];
    const float* whh1 = (const float*)d_in[12];
    const float* bih1 = (const float*)d_in[13];
    const float* bhh1 = (const float*)d_in[14];
    const float* fc_w = (const float*)d_in[15];
    const float* fc_b = (const float*)d_in[16];
    float* out = (float*)d_out;

    convertw_kernel<<<368, 256>>>(wih0, whh0, wih1, whh1, Wq);
    init_kernel<<<40, 256>>>(h0, c0, Wq);
    gemm_kv_kernel<<<dim3(8, 128, 2), 256>>>(enc, Wk, Wv);
    // scores for step 0 (uses q from init)
    scores_kernel<<<dim3(16, 32), 256>>>(We);

    for (int s = 0; s < SDEC; s++) {
        int p = s & 1;
        ctx_kernel<<<dim3(8, 32), 1024>>>();
        lstm0_kernel<<<128, 512>>>(bih0, bhh0, p);
        lstm1q_kernel<<<192, 512>>>(bih1, bhh1, p);
        // fc for this step + scores for next step (last iteration's scores unused)
        fcscores_kernel<<<528, 256>>>(fc_w, fc_b, We, out, s, p);
    }
}

// round 15
// speedup vs baseline: 1.3533x; 1.3533x over previous
#include <cuda_runtime.h>
#include <cuda_fp16.h>
#include <mma.h>

using namespace nvcuda;

#define BB   32
#define TT   512
#define HHD  512
#define KVD  1024
#define OUTD 128
#define XKD  1152   // OUT + KV
#define SDEC 128

// ---------------- static scratch ----------------
__device__ __half g_key[BB*TT*KVD];           // 33.5 MB (fp16)
__device__ __half g_val[BB*TT*KVD];           // 33.5 MB (fp16)
__device__ alignas(16) __half g_wih0h[2048*XKD];
__device__ alignas(16) __half g_whh0h[2048*HHD];
__device__ alignas(16) __half g_wih1h[2048*HHD];
__device__ alignas(16) __half g_whh1h[2048*HHD];
__device__ alignas(16) __half g_wqh[KVD*HHD];
__device__ float g_q[BB*KVD];
__device__ float g_scores[BB*TT];
__device__ float g_xT[(XKD/4)*BB*4];          // x=[y,ctx] grouped-4 transposed
__device__ float g_h0T[2][(HHD/4)*BB*4];      // ping-pong
__device__ float g_h1T[2][(HHD/4)*BB*4];
__device__ float g_c0[HHD*BB];                // [u][b]
__device__ float g_c1[HHD*BB];

__device__ __forceinline__ float fast_tanh(float x) {      // accurate (LSTM cells)
    float e = __expf(2.0f * x);
    return 1.0f - __fdividef(2.0f, e + 1.0f);
}
__device__ __forceinline__ float tanha(float x) {          // HW MUFU (scores)
    float y; asm("tanh.approx.f32 %0, %1;" : "=f"(y) : "f"(x)); return y;
}
__device__ __forceinline__ float sigm(float x) {
    return __fdividef(1.0f, 1.0f + __expf(-x));
}
__device__ __forceinline__ float dot4(float4 a, float4 b) {
    return a.x*b.x + a.y*b.y + a.z*b.z + a.w*b.w;
}
// dot of 4 halves (packed in uint2) with float4
__device__ __forceinline__ float dot4h(uint2 wv, float4 x) {
    __half2* hp = (__half2*)&wv;
    float2 a = __half22float2(hp[0]);
    float2 b = __half22float2(hp[1]);
    return a.x * x.x + a.y * x.y + b.x * x.z + b.y * x.w;
}
// grouped-4 transposed float index for (k, batch m)
__device__ __forceinline__ int idx4(int k, int m) { return ((k >> 2) << 7) + (m << 2) + (k & 3); }

// ---------------------------------------------------------------
// convert weights to fp16 (one-time): 16384 floats per block
// ---------------------------------------------------------------
__global__ void __launch_bounds__(256) convertw_kernel(const float* __restrict__ wih0,
                                                       const float* __restrict__ whh0,
                                                       const float* __restrict__ wih1,
                                                       const float* __restrict__ whh1,
                                                       const float* __restrict__ Wq) {
    int bx = blockIdx.x;
    const float* src; __half* dst; size_t off;
    if (bx < 144)      { src = wih0; dst = g_wih0h; off = (size_t)bx * 16384; }
    else if (bx < 208) { src = whh0; dst = g_whh0h; off = (size_t)(bx - 144) * 16384; }
    else if (bx < 272) { src = wih1; dst = g_wih1h; off = (size_t)(bx - 208) * 16384; }
    else if (bx < 336) { src = whh1; dst = g_whh1h; off = (size_t)(bx - 272) * 16384; }
    else               { src = Wq;   dst = g_wqh;   off = (size_t)(bx - 336) * 16384; }
    const float4* s4 = (const float4*)(src + off);
    for (int i = threadIdx.x; i < 4096; i += 256) {
        float4 v = __ldg(s4 + i);
        union { __half h[4]; uint2 u; } pk;
        pk.h[0] = __float2half_rn(v.x); pk.h[1] = __float2half_rn(v.y);
        pk.h[2] = __float2half_rn(v.z); pk.h[3] = __float2half_rn(v.w);
        *(uint2*)(dst + off + (size_t)i * 4) = pk.u;
    }
}

// ---------------------------------------------------------------
// init: blocks 0..31 -> q0 = h0[0] @ Wq^T ; blocks 32..39 -> state transpose + y0=0
// ---------------------------------------------------------------
__global__ void init_kernel(const float* __restrict__ h0, const float* __restrict__ c0,
                            const float* __restrict__ Wq) {
    int bx = blockIdx.x, tid = threadIdx.x;
    if (bx < 32) {
        __shared__ float sh[512];
        for (int p = tid; p < 512; p += 256) sh[p] = h0[bx * 512 + p];
        __syncthreads();
        int w = tid >> 5, lane = tid & 31;
        const float4* shv = (const float4*)sh;
        for (int jj = 0; jj < 128; jj++) {
            int j = (w << 7) + jj;
            const float4* wq = (const float4*)(Wq + (size_t)j * 512);
            float acc = 0.f;
#pragma unroll
            for (int i = 0; i < 4; i++)
                acc += dot4(__ldg(&wq[lane + (i << 5)]), shv[lane + (i << 5)]);
#pragma unroll
            for (int off = 16; off; off >>= 1) acc += __shfl_xor_sync(0xffffffffu, acc, off);
            if (lane == 0) g_q[(bx << 10) + j] = acc;
        }
    } else {
        int p0 = (bx - 32) * 256 + tid;
        for (int i = p0; i < BB * HHD; i += 8 * 256) {
            int b = i >> 9, u = i & 511;
            int ix = idx4(u, b);
            g_h0T[0][ix] = h0[i];
            g_h1T[0][ix] = h0[BB * HHD + i];
            g_c0[u * 32 + b] = c0[i];
            g_c1[u * 32 + b] = c0[BB * HHD + i];
        }
        for (int i = p0; i < OUTD * 32; i += 8 * 256) g_xT[i] = 0.f;
    }
}

// ---------------------------------------------------------------
// key/value precompute via WMMA, double-buffered software pipeline
// ---------------------------------------------------------------
__global__ void __launch_bounds__(256) gemm_kv_kernel(const float* __restrict__ A,
                                                      const float* __restrict__ Wk,
                                                      const float* __restrict__ Wv) {
    const float* W = blockIdx.z ? Wv : Wk;
    __half* C = blockIdx.z ? g_val : g_key;
    int m0 = blockIdx.y << 7, n0 = blockIdx.x << 7;
    __shared__ alignas(256) __half As[2][128][40];
    __shared__ alignas(256) __half Bs[2][128][40];
    __shared__ alignas(256) float stage[8][256];
    int tid = threadIdx.x, lane = tid & 31, wid = tid >> 5;
    int wm = (wid & 3) << 5;
    int wn = (wid >> 2) << 6;

    wmma::fragment<wmma::accumulator, 16, 16, 16, float> acc[2][4];
#pragma unroll
    for (int mf = 0; mf < 2; mf++)
#pragma unroll
        for (int nf = 0; nf < 4; nf++) wmma::fill_fragment(acc[mf][nf], 0.0f);

    int r = tid & 127;
    const float* srcrow = (tid < 128) ? (A + (size_t)(m0 + r) * 1024)
                                      : (W + (size_t)(n0 + r) * 1024);

    float4 f[8];
#define GEMM_LOAD(k0)                                                   \
    {                                                                   \
        _Pragma("unroll")                                               \
        for (int j = 0; j < 4; j++) {                                   \
            f[2*j]   = __ldg((const float4*)(srcrow + (k0) + j * 8));   \
            f[2*j+1] = __ldg((const float4*)(srcrow + (k0) + j * 8 + 4));\
        }                                                               \
    }
#define GEMM_STORE(buf)                                                 \
    {                                                                   \
        __half* dstrow = (tid < 128) ? &As[buf][r][0] : &Bs[buf][r][0]; \
        _Pragma("unroll")                                               \
        for (int j = 0; j < 4; j++) {                                   \
            union { __half h[8]; uint4 u; } pk;                         \
            pk.h[0] = __float2half_rn(f[2*j].x);                        \
            pk.h[1] = __float2half_rn(f[2*j].y);                        \
            pk.h[2] = __float2half_rn(f[2*j].z);                        \
            pk.h[3] = __float2half_rn(f[2*j].w);                        \
            pk.h[4] = __float2half_rn(f[2*j+1].x);                      \
            pk.h[5] = __float2half_rn(f[2*j+1].y);                      \
            pk.h[6] = __float2half_rn(f[2*j+1].z);                      \
            pk.h[7] = __float2half_rn(f[2*j+1].w);                      \
            *(uint4*)(dstrow + j * 8) = pk.u;                           \
        }                                                               \
    }

    GEMM_LOAD(0);
    GEMM_STORE(0);
    __syncthreads();

    for (int c = 0; c < 32; c++) {
        if (c < 31) GEMM_LOAD((c + 1) << 5);
        int buf = c & 1;
#pragma unroll
        for (int ks = 0; ks < 32; ks += 16) {
            wmma::fragment<wmma::matrix_a, 16, 16, 16, __half, wmma::row_major> af[2];
            wmma::fragment<wmma::matrix_b, 16, 16, 16, __half, wmma::col_major> bf[4];
#pragma unroll
            for (int mf = 0; mf < 2; mf++)
                wmma::load_matrix_sync(af[mf], &As[buf][wm + (mf << 4)][ks], 40);
#pragma unroll
            for (int nf = 0; nf < 4; nf++)
                wmma::load_matrix_sync(bf[nf], &Bs[buf][wn + (nf << 4)][ks], 40);
#pragma unroll
            for (int mf = 0; mf < 2; mf++)
#pragma unroll
                for (int nf = 0; nf < 4; nf++)
                    wmma::mma_sync(acc[mf][nf], af[mf], bf[nf], acc[mf][nf]);
        }
        if (c < 31) GEMM_STORE((c + 1) & 1);
        __syncthreads();
    }
#undef GEMM_LOAD
#undef GEMM_STORE

#pragma unroll
    for (int mf = 0; mf < 2; mf++)
#pragma unroll
        for (int nf = 0; nf < 4; nf++) {
            wmma::store_matrix_sync(stage[wid], acc[mf][nf], 16, wmma::mem_row_major);
            __syncwarp();
#pragma unroll
            for (int i = lane; i < 128; i += 32) {
                int rr = i >> 3, c2 = (i & 7) << 1;
                __half2 h = __floats2half2_rn(stage[wid][rr * 16 + c2],
                                              stage[wid][rr * 16 + c2 + 1]);
                *(__half2*)(C + (size_t)(m0 + wm + (mf << 4) + rr) * 1024
                              + n0 + wn + (nf << 4) + c2) = h;
            }
            __syncwarp();
        }
}

// ---------------------------------------------------------------
// scores body (R12 version): 256 threads; (chunk, b) = 32-t slab; warp 4 rows
// ---------------------------------------------------------------
__device__ __forceinline__ void scores_body(const float* __restrict__ We,
                                            int chunk, int b, int tid,
                                            float* sq, float* swe) {
    for (int p = tid; p < 1024; p += 256) { sq[p] = g_q[(b << 10) + p]; swe[p] = We[p]; }
    __syncthreads();
    int w = tid >> 5, lane = tid & 31;
    const float4* qv = (const float4*)sq;
    const float4* wv = (const float4*)swe;
#pragma unroll
    for (int r = 0; r < 4; r++) {
        int t = (chunk << 5) + (w << 2) + r;
        const uint4* kp = (const uint4*)(g_key + ((size_t)(b * 512 + t) << 10));
        uint4 kk[4];
#pragma unroll
        for (int i = 0; i < 4; i++) kk[i] = __ldg(&kp[lane + (i << 5)]);
        float acc = 0.f;
#pragma unroll
        for (int i = 0; i < 4; i++) {
            int q4 = (lane + (i << 5)) << 1;
            float4 qa = qv[q4],     qb = qv[q4 + 1];
            float4 wa = wv[q4],     wb = wv[q4 + 1];
            const __half2* hp = (const __half2*)&kk[i];
            float2 f0 = __half22float2(hp[0]);
            float2 f1 = __half22float2(hp[1]);
            float2 f2 = __half22float2(hp[2]);
            float2 f3 = __half22float2(hp[3]);
            acc += wa.x * tanha(qa.x + f0.x);
            acc += wa.y * tanha(qa.y + f0.y);
            acc += wa.z * tanha(qa.z + f1.x);
            acc += wa.w * tanha(qa.w + f1.y);
            acc += wb.x * tanha(qb.x + f2.x);
            acc += wb.y * tanha(qb.y + f2.y);
            acc += wb.z * tanha(qb.z + f3.x);
            acc += wb.w * tanha(qb.w + f3.y);
        }
#pragma unroll
        for (int off = 16; off; off >>= 1) acc += __shfl_xor_sync(0xffffffffu, acc, off);
        if (lane == 0) g_scores[(b << 9) + t] = acc;
    }
}

__global__ void __launch_bounds__(256) scores_kernel(const float* __restrict__ We) {
    __shared__ float sq[1024], swe[1024];
    scores_body(We, blockIdx.x, blockIdx.y, threadIdx.x, sq, swe);
}

// ---------------------------------------------------------------
// softmax + context (R12 version): grid (8,32), 1024 threads, 64 t-phases
// ---------------------------------------------------------------
__global__ void __launch_bounds__(1024) ctx_kernel() {
    int b = blockIdx.y, tid = threadIdx.x;
    int lane = tid & 31, wid = tid >> 5;
    __shared__ float sal[512];
    __shared__ float racc[64 * 128];
    __shared__ float part2[1024];
    __shared__ float wm[32], ws[32];

    float v = (tid < 512) ? g_scores[(b << 9) + tid] : -1e30f;
    float m = v;
#pragma unroll
    for (int o = 16; o; o >>= 1) m = fmaxf(m, __shfl_xor_sync(0xffffffffu, m, o));
    if (lane == 0) wm[wid] = m;
    __syncthreads();
    if (tid < 32) {
        float x = wm[tid];
#pragma unroll
        for (int o = 16; o; o >>= 1) x = fmaxf(x, __shfl_xor_sync(0xffffffffu, x, o));
        wm[tid] = x;
    }
    __syncthreads();
    float mx = wm[0];
    float e = (tid < 512) ? __expf(v - mx) : 0.f;
    if (tid < 512) sal[tid] = e;
    float s = e;
#pragma unroll
    for (int o = 16; o; o >>= 1) s += __shfl_xor_sync(0xffffffffu, s, o);
    if (lane == 0) ws[wid] = s;
    __syncthreads();
    if (tid < 32) {
        float x = ws[tid];
#pragma unroll
        for (int o = 16; o; o >>= 1) x += __shfl_xor_sync(0xffffffffu, x, o);
        ws[tid] = x;
    }
    __syncthreads();
    float inv = __fdividef(1.0f, ws[0]);

    int tph = (wid << 1) + (lane >> 4);
    int dl  = lane & 15;
    const uint4* vp = (const uint4*)g_val + ((size_t)b << 16) + (blockIdx.x << 4) + dl;
    float a0=0,a1=0,a2=0,a3=0,a4=0,a5=0,a6=0,a7=0;
#pragma unroll
    for (int t = tph; t < 512; t += 64) {
        uint4 vv = __ldg(vp + ((size_t)t << 7));
        float sc = sal[t];
        const __half2* hp = (const __half2*)&vv;
        float2 f0 = __half22float2(hp[0]);
        float2 f1 = __half22float2(hp[1]);
        float2 f2 = __half22float2(hp[2]);
        float2 f3 = __half22float2(hp[3]);
        a0 += sc * f0.x; a1 += sc * f0.y; a2 += sc * f1.x; a3 += sc * f1.y;
        a4 += sc * f2.x; a5 += sc * f2.y; a6 += sc * f3.x; a7 += sc * f3.y;
    }
    float4* r4 = (float4*)racc;
    int base4 = (tph << 5) + (dl << 1);
    r4[base4]     = make_float4(a0, a1, a2, a3);
    r4[base4 + 1] = make_float4(a4, a5, a6, a7);
    __syncthreads();

    {
        int d = tid & 127, g = tid >> 7;
        float sum = 0.f;
#pragma unroll
        for (int i = 0; i < 8; i++) sum += racc[((g + (i << 3)) << 7) + d];
        part2[(g << 7) + d] = sum;
    }
    __syncthreads();
    if (tid < 128) {
        float sum = 0.f;
#pragma unroll
        for (int g = 0; g < 8; g++) sum += part2[(g << 7) + tid];
        int k = 128 + (blockIdx.x << 7) + tid;
        g_xT[((k >> 2) << 7) + (b << 2) + (k & 3)] = sum * inv;
    }
}

// ---------------------------------------------------------------
// lstm0: grid 256 (2 units/block), 512 threads = 16 warps (each a k-slice);
// every activation float4 is loaded once and applied to BOTH units' 4 gates.
// Same total threads/warps as the 7462us config; activation L2 traffic halved.
// ---------------------------------------------------------------
__global__ void __launch_bounds__(512) lstm0_kernel(const float* __restrict__ bih,
                                                    const float* __restrict__ bhh,
                                                    int p) {
    __shared__ float part[2][4][16][32];   // 16 KB
    int tid = threadIdx.x, wid = tid >> 5, lane = tid & 31;
    int u0 = blockIdx.x << 1;
    const float4* xT4 = (const float4*)g_xT;
    const float4* hT4 = (const float4*)g_h0T[p];
    const uint2* wihv = (const uint2*)g_wih0h;   // 288 uint2 per row
    const uint2* whhv = (const uint2*)g_whh0h;   // 128 uint2 per row
    float acc[2][4] = {{0.f,0.f,0.f,0.f},{0.f,0.f,0.f,0.f}};

    // ih: 288 groups, 18 per warp
    for (int g = wid * 18; g < wid * 18 + 18; g++) {
        float4 xv = xT4[(g << 5) + lane];
#pragma unroll
        for (int un = 0; un < 2; un++)
#pragma unroll
            for (int gate = 0; gate < 4; gate++)
                acc[un][gate] += dot4h(__ldg(&wihv[(size_t)(gate * 512 + u0 + un) * 288 + g]), xv);
    }
    // hh: 128 groups, 8 per warp
    for (int g = wid * 8; g < wid * 8 + 8; g++) {
        float4 hv = hT4[(g << 5) + lane];
#pragma unroll
        for (int un = 0; un < 2; un++)
#pragma unroll
            for (int gate = 0; gate < 4; gate++)
                acc[un][gate] += dot4h(__ldg(&whhv[(size_t)(gate * 512 + u0 + un) * 128 + g]), hv);
    }
#pragma unroll
    for (int un = 0; un < 2; un++)
#pragma unroll
        for (int gate = 0; gate < 4; gate++) part[un][gate][wid][lane] = acc[un][gate];
    __syncthreads();
    if (wid < 2) {
        int uf = u0 + wid;
        float gv[4];
#pragma unroll
        for (int gate = 0; gate < 4; gate++) {
            int j = gate * 512 + uf;
            float s = 0.f;
#pragma unroll
            for (int i = 0; i < 16; i++) s += part[wid][gate][i][lane];
            gv[gate] = s + bih[j] + bhh[j];
        }
        float c = g_c0[uf * 32 + lane];
        float cn = sigm(gv[1]) * c + sigm(gv[0]) * fast_tanh(gv[2]);
        float hn = sigm(gv[3]) * fast_tanh(cn);
        g_c0[uf * 32 + lane] = cn;
        g_h0T[1 - p][idx4(uf, lane)] = hn;
    }
}

// ---------------------------------------------------------------
// lstm1 (+ q-projection): blocks<256 lstm (2 units/block, 16 k-slices),
// blocks 256..319 qproj (16 warps, one j per warp)
// ---------------------------------------------------------------
__global__ void __launch_bounds__(512) lstm1q_kernel(const float* __restrict__ bih,
                                                     const float* __restrict__ bhh,
                                                     int p) {
    int tid = threadIdx.x, wid = tid >> 5, lane = tid & 31;
    const float4* h0n = (const float4*)g_h0T[1 - p];
    if (blockIdx.x < 256) {
        __shared__ float part[2][4][16][32];
        int u0 = blockIdx.x << 1;
        const float4* hT4 = (const float4*)g_h1T[p];
        const uint2* wihv = (const uint2*)g_wih1h;   // 128 uint2 per row
        const uint2* whhv = (const uint2*)g_whh1h;
        float acc[2][4] = {{0.f,0.f,0.f,0.f},{0.f,0.f,0.f,0.f}};
        // 128 groups, 8 per warp
        for (int g = wid * 8; g < wid * 8 + 8; g++) {
            float4 xv = h0n[(g << 5) + lane];
            float4 hv = hT4[(g << 5) + lane];
#pragma unroll
            for (int un = 0; un < 2; un++)
#pragma unroll
                for (int gate = 0; gate < 4; gate++) {
                    int j = gate * 512 + u0 + un;
                    acc[un][gate] += dot4h(__ldg(&wihv[(size_t)j * 128 + g]), xv);
                    acc[un][gate] += dot4h(__ldg(&whhv[(size_t)j * 128 + g]), hv);
                }
        }
#pragma unroll
        for (int un = 0; un < 2; un++)
#pragma unroll
            for (int gate = 0; gate < 4; gate++) part[un][gate][wid][lane] = acc[un][gate];
        __syncthreads();
        if (wid < 2) {
            int uf = u0 + wid;
            float gv[4];
#pragma unroll
            for (int gate = 0; gate < 4; gate++) {
                int j = gate * 512 + uf;
                float s = 0.f;
#pragma unroll
                for (int i = 0; i < 16; i++) s += part[wid][gate][i][lane];
                gv[gate] = s + bih[j] + bhh[j];
            }
            float c = g_c1[uf * 32 + lane];
            float cn = sigm(gv[1]) * c + sigm(gv[0]) * fast_tanh(gv[2]);
            float hn = sigm(gv[3]) * fast_tanh(cn);
            g_c1[uf * 32 + lane] = cn;
            g_h1T[1 - p][idx4(uf, lane)] = hn;
        }
    } else {
        // q projection: q = h0n @ Wq^T (fp16 Wq), one warp per output feature j
        int j = (blockIdx.x - 256) * 16 + wid;
        const uint2* wq = (const uint2*)(g_wqh + (size_t)j * 512);
        float acc = 0.f;
        for (int g = 0; g < 128; g++)
            acc += dot4h(__ldg(&wq[g]), h0n[(g << 5) + lane]);
        g_q[lane * 1024 + j] = acc;
    }
}

// ---------------------------------------------------------------
// fused fc (this step) + scores (next step)  (R12 version)
// ---------------------------------------------------------------
__global__ void __launch_bounds__(256) fcscores_kernel(const float* __restrict__ fc_w,
                                                       const float* __restrict__ fc_b,
                                                       const float* __restrict__ We,
                                                       float* __restrict__ out, int s, int p) {
    __shared__ float sq[1024], swe[1024];
    if (blockIdx.x < 16) {
        int w = threadIdx.x >> 5, lane = threadIdx.x & 31;
        int o = blockIdx.x * 8 + w;
        const float4* h1n = (const float4*)g_h1T[1 - p];
        const float4* fw = (const float4*)(fc_w + (size_t)o * 512);
        float acc = 0.f;
        for (int g = 0; g < 128; g++)
            acc += dot4(__ldg(&fw[g]), h1n[(g << 5) + lane]);
        float y = fmaxf(acc + fc_b[o], 0.f);
        out[(size_t)lane * (SDEC * OUTD) + s * OUTD + o] = y;
        g_xT[idx4(o, lane)] = 1.0f + y;
    } else {
        int idx = blockIdx.x - 16;
        scores_body(We, idx & 15, idx >> 4, threadIdx.x, sq, swe);
    }
}

// ---------------------------------------------------------------
extern "C" void kernel_launch(void* const* d_in, const int* in_sizes, int n_in,
                              void* d_out, int out_size) {
    const float* enc  = (const float*)d_in[0];
    const float* h0   = (const float*)d_in[1];
    const float* c0   = (const float*)d_in[2];
    const float* Wk   = (const float*)d_in[3];
    const float* Wq   = (const float*)d_in[4];
    const float* Wv   = (const float*)d_in[5];
    const float* We   = (const float*)d_in[6];
    const float* wih0 = (const float*)d_in[7];
    const float* whh0 = (const float*)d_in[8];
    const float* bih0 = (const float*)d_in[9];
    const float* bhh0 = (const float*)d_in[10];
    const float* wih1 = (const float*)d_in[11];
    const float* whh1 = (const float*)d_in[12];
    const float* bih1 = (const float*)d_in[13];
    const float* bhh1 = (const float*)d_in[14];
    const float* fc_w = (const float*)d_in[15];
    const float* fc_b = (const float*)d_in[16];
    float* out = (float*)d_out;

    convertw_kernel<<<368, 256>>>(wih0, whh0, wih1, whh1, Wq);
    init_kernel<<<40, 256>>>(h0, c0, Wq);
    gemm_kv_kernel<<<dim3(8, 128, 2), 256>>>(enc, Wk, Wv);
    // scores for step 0 (uses q from init)
    scores_kernel<<<dim3(16, 32), 256>>>(We);

    for (int s = 0; s < SDEC; s++) {
        int p = s & 1;
        ctx_kernel<<<dim3(8, 32), 1024>>>();
        lstm0_kernel<<<256, 512>>>(bih0, bhh0, p);
        lstm1q_kernel<<<320, 512>>>(bih1, bhh1, p);
        // fc for this step + scores for next step (last iteration's scores unused)
        fcscores_kernel<<<528, 256>>>(fc_w, fc_b, We, out, s, p);
    }
}

// round 16
// speedup vs baseline: 1.5075x; 1.1140x over previous
#include <cuda_runtime.h>
#include <cuda_fp16.h>
#include <mma.h>

using namespace nvcuda;

#define BB   32
#define TT   512
#define HHD  512
#define KVD  1024
#define OUTD 128
#define XKD  1152   // OUT + KV
#define SDEC 128

// ---------------- static scratch ----------------
__device__ __half g_key[BB*TT*KVD];           // 33.5 MB (fp16)
__device__ __half g_val[BB*TT*KVD];           // 33.5 MB (fp16)
__device__ alignas(16) __half g_wih0h[2048*XKD];
__device__ alignas(16) __half g_whh0h[2048*HHD];
__device__ alignas(16) __half g_wih1h[2048*HHD];
__device__ alignas(16) __half g_whh1h[2048*HHD];
__device__ alignas(16) __half g_wqh[KVD*HHD];
__device__ float g_q[BB*KVD];
__device__ float g_scores[BB*TT];
__device__ float g_xT[(XKD/4)*BB*4];          // x=[y,ctx] grouped-4 transposed
__device__ float g_h0T[2][(HHD/4)*BB*4];      // ping-pong
__device__ float g_h1T[2][(HHD/4)*BB*4];
__device__ float g_c0[HHD*BB];                // [u][b]
__device__ float g_c1[HHD*BB];

__device__ __forceinline__ float fast_tanh(float x) {      // accurate (LSTM cells)
    float e = __expf(2.0f * x);
    return 1.0f - __fdividef(2.0f, e + 1.0f);
}
__device__ __forceinline__ float tanha(float x) {          // HW MUFU (scores)
    float y; asm("tanh.approx.f32 %0, %1;" : "=f"(y) : "f"(x)); return y;
}
__device__ __forceinline__ float sigm(float x) {
    return __fdividef(1.0f, 1.0f + __expf(-x));
}
__device__ __forceinline__ float dot4(float4 a, float4 b) {
    return a.x*b.x + a.y*b.y + a.z*b.z + a.w*b.w;
}
// dot of 4 halves (packed in uint2) with float4
__device__ __forceinline__ float dot4h(uint2 wv, float4 x) {
    __half2* hp = (__half2*)&wv;
    float2 a = __half22float2(hp[0]);
    float2 b = __half22float2(hp[1]);
    return a.x * x.x + a.y * x.y + b.x * x.z + b.y * x.w;
}
// grouped-4 transposed float index for (k, batch m)
__device__ __forceinline__ int idx4(int k, int m) { return ((k >> 2) << 7) + (m << 2) + (k & 3); }

// ---------------------------------------------------------------
// convert weights to fp16 (one-time): 16384 floats per block
// ---------------------------------------------------------------
__global__ void __launch_bounds__(256) convertw_kernel(const float* __restrict__ wih0,
                                                       const float* __restrict__ whh0,
                                                       const float* __restrict__ wih1,
                                                       const float* __restrict__ whh1,
                                                       const float* __restrict__ Wq) {
    int bx = blockIdx.x;
    const float* src; __half* dst; size_t off;
    if (bx < 144)      { src = wih0; dst = g_wih0h; off = (size_t)bx * 16384; }
    else if (bx < 208) { src = whh0; dst = g_whh0h; off = (size_t)(bx - 144) * 16384; }
    else if (bx < 272) { src = wih1; dst = g_wih1h; off = (size_t)(bx - 208) * 16384; }
    else if (bx < 336) { src = whh1; dst = g_whh1h; off = (size_t)(bx - 272) * 16384; }
    else               { src = Wq;   dst = g_wqh;   off = (size_t)(bx - 336) * 16384; }
    const float4* s4 = (const float4*)(src + off);
    for (int i = threadIdx.x; i < 4096; i += 256) {
        float4 v = __ldg(s4 + i);
        union { __half h[4]; uint2 u; } pk;
        pk.h[0] = __float2half_rn(v.x); pk.h[1] = __float2half_rn(v.y);
        pk.h[2] = __float2half_rn(v.z); pk.h[3] = __float2half_rn(v.w);
        *(uint2*)(dst + off + (size_t)i * 4) = pk.u;
    }
}

// ---------------------------------------------------------------
// init: blocks 0..31 -> q0 = h0[0] @ Wq^T ; blocks 32..39 -> state transpose + y0=0
// ---------------------------------------------------------------
__global__ void init_kernel(const float* __restrict__ h0, const float* __restrict__ c0,
                            const float* __restrict__ Wq) {
    int bx = blockIdx.x, tid = threadIdx.x;
    if (bx < 32) {
        __shared__ float sh[512];
        for (int p = tid; p < 512; p += 256) sh[p] = h0[bx * 512 + p];
        __syncthreads();
        int w = tid >> 5, lane = tid & 31;
        const float4* shv = (const float4*)sh;
        for (int jj = 0; jj < 128; jj++) {
            int j = (w << 7) + jj;
            const float4* wq = (const float4*)(Wq + (size_t)j * 512);
            float acc = 0.f;
#pragma unroll
            for (int i = 0; i < 4; i++)
                acc += dot4(__ldg(&wq[lane + (i << 5)]), shv[lane + (i << 5)]);
#pragma unroll
            for (int off = 16; off; off >>= 1) acc += __shfl_xor_sync(0xffffffffu, acc, off);
            if (lane == 0) g_q[(bx << 10) + j] = acc;
        }
    } else {
        int p0 = (bx - 32) * 256 + tid;
        for (int i = p0; i < BB * HHD; i += 8 * 256) {
            int b = i >> 9, u = i & 511;
            int ix = idx4(u, b);
            g_h0T[0][ix] = h0[i];
            g_h1T[0][ix] = h0[BB * HHD + i];
            g_c0[u * 32 + b] = c0[i];
            g_c1[u * 32 + b] = c0[BB * HHD + i];
        }
        for (int i = p0; i < OUTD * 32; i += 8 * 256) g_xT[i] = 0.f;
    }
}

// ---------------------------------------------------------------
// key/value precompute via WMMA, double-buffered software pipeline
// ---------------------------------------------------------------
__global__ void __launch_bounds__(256) gemm_kv_kernel(const float* __restrict__ A,
                                                      const float* __restrict__ Wk,
                                                      const float* __restrict__ Wv) {
    const float* W = blockIdx.z ? Wv : Wk;
    __half* C = blockIdx.z ? g_val : g_key;
    int m0 = blockIdx.y << 7, n0 = blockIdx.x << 7;
    __shared__ alignas(256) __half As[2][128][40];
    __shared__ alignas(256) __half Bs[2][128][40];
    __shared__ alignas(256) float stage[8][256];
    int tid = threadIdx.x, lane = tid & 31, wid = tid >> 5;
    int wm = (wid & 3) << 5;
    int wn = (wid >> 2) << 6;

    wmma::fragment<wmma::accumulator, 16, 16, 16, float> acc[2][4];
#pragma unroll
    for (int mf = 0; mf < 2; mf++)
#pragma unroll
        for (int nf = 0; nf < 4; nf++) wmma::fill_fragment(acc[mf][nf], 0.0f);

    int r = tid & 127;
    const float* srcrow = (tid < 128) ? (A + (size_t)(m0 + r) * 1024)
                                      : (W + (size_t)(n0 + r) * 1024);

    float4 f[8];
#define GEMM_LOAD(k0)                                                   \
    {                                                                   \
        _Pragma("unroll")                                               \
        for (int j = 0; j < 4; j++) {                                   \
            f[2*j]   = __ldg((const float4*)(srcrow + (k0) + j * 8));   \
            f[2*j+1] = __ldg((const float4*)(srcrow + (k0) + j * 8 + 4));\
        }                                                               \
    }
#define GEMM_STORE(buf)                                                 \
    {                                                                   \
        __half* dstrow = (tid < 128) ? &As[buf][r][0] : &Bs[buf][r][0]; \
        _Pragma("unroll")                                               \
        for (int j = 0; j < 4; j++) {                                   \
            union { __half h[8]; uint4 u; } pk;                         \
            pk.h[0] = __float2half_rn(f[2*j].x);                        \
            pk.h[1] = __float2half_rn(f[2*j].y);                        \
            pk.h[2] = __float2half_rn(f[2*j].z);                        \
            pk.h[3] = __float2half_rn(f[2*j].w);                        \
            pk.h[4] = __float2half_rn(f[2*j+1].x);                      \
            pk.h[5] = __float2half_rn(f[2*j+1].y);                      \
            pk.h[6] = __float2half_rn(f[2*j+1].z);                      \
            pk.h[7] = __float2half_rn(f[2*j+1].w);                      \
            *(uint4*)(dstrow + j * 8) = pk.u;                           \
        }                                                               \
    }

    GEMM_LOAD(0);
    GEMM_STORE(0);
    __syncthreads();

    for (int c = 0; c < 32; c++) {
        if (c < 31) GEMM_LOAD((c + 1) << 5);
        int buf = c & 1;
#pragma unroll
        for (int ks = 0; ks < 32; ks += 16) {
            wmma::fragment<wmma::matrix_a, 16, 16, 16, __half, wmma::row_major> af[2];
            wmma::fragment<wmma::matrix_b, 16, 16, 16, __half, wmma::col_major> bf[4];
#pragma unroll
            for (int mf = 0; mf < 2; mf++)
                wmma::load_matrix_sync(af[mf], &As[buf][wm + (mf << 4)][ks], 40);
#pragma unroll
            for (int nf = 0; nf < 4; nf++)
                wmma::load_matrix_sync(bf[nf], &Bs[buf][wn + (nf << 4)][ks], 40);
#pragma unroll
            for (int mf = 0; mf < 2; mf++)
#pragma unroll
                for (int nf = 0; nf < 4; nf++)
                    wmma::mma_sync(acc[mf][nf], af[mf], bf[nf], acc[mf][nf]);
        }
        if (c < 31) GEMM_STORE((c + 1) & 1);
        __syncthreads();
    }
#undef GEMM_LOAD
#undef GEMM_STORE

#pragma unroll
    for (int mf = 0; mf < 2; mf++)
#pragma unroll
        for (int nf = 0; nf < 4; nf++) {
            wmma::store_matrix_sync(stage[wid], acc[mf][nf], 16, wmma::mem_row_major);
            __syncwarp();
#pragma unroll
            for (int i = lane; i < 128; i += 32) {
                int rr = i >> 3, c2 = (i & 7) << 1;
                __half2 h = __floats2half2_rn(stage[wid][rr * 16 + c2],
                                              stage[wid][rr * 16 + c2 + 1]);
                *(__half2*)(C + (size_t)(m0 + wm + (mf << 4) + rr) * 1024
                              + n0 + wn + (nf << 4) + c2) = h;
            }
            __syncwarp();
        }
}

// ---------------------------------------------------------------
// scores body (R12 version): 256 threads; (chunk, b) = 32-t slab; warp 4 rows
// ---------------------------------------------------------------
__device__ __forceinline__ void scores_body(const float* __restrict__ We,
                                            int chunk, int b, int tid,
                                            float* sq, float* swe) {
    for (int p = tid; p < 1024; p += 256) { sq[p] = g_q[(b << 10) + p]; swe[p] = We[p]; }
    __syncthreads();
    int w = tid >> 5, lane = tid & 31;
    const float4* qv = (const float4*)sq;
    const float4* wv = (const float4*)swe;
#pragma unroll
    for (int r = 0; r < 4; r++) {
        int t = (chunk << 5) + (w << 2) + r;
        const uint4* kp = (const uint4*)(g_key + ((size_t)(b * 512 + t) << 10));
        uint4 kk[4];
#pragma unroll
        for (int i = 0; i < 4; i++) kk[i] = __ldg(&kp[lane + (i << 5)]);
        float acc = 0.f;
#pragma unroll
        for (int i = 0; i < 4; i++) {
            int q4 = (lane + (i << 5)) << 1;
            float4 qa = qv[q4],     qb = qv[q4 + 1];
            float4 wa = wv[q4],     wb = wv[q4 + 1];
            const __half2* hp = (const __half2*)&kk[i];
            float2 f0 = __half22float2(hp[0]);
            float2 f1 = __half22float2(hp[1]);
            float2 f2 = __half22float2(hp[2]);
            float2 f3 = __half22float2(hp[3]);
            acc += wa.x * tanha(qa.x + f0.x);
            acc += wa.y * tanha(qa.y + f0.y);
            acc += wa.z * tanha(qa.z + f1.x);
            acc += wa.w * tanha(qa.w + f1.y);
            acc += wb.x * tanha(qb.x + f2.x);
            acc += wb.y * tanha(qb.y + f2.y);
            acc += wb.z * tanha(qb.z + f3.x);
            acc += wb.w * tanha(qb.w + f3.y);
        }
#pragma unroll
        for (int off = 16; off; off >>= 1) acc += __shfl_xor_sync(0xffffffffu, acc, off);
        if (lane == 0) g_scores[(b << 9) + t] = acc;
    }
}

__global__ void __launch_bounds__(256) scores_kernel(const float* __restrict__ We) {
    __shared__ float sq[1024], swe[1024];
    scores_body(We, blockIdx.x, blockIdx.y, threadIdx.x, sq, swe);
}

// ---------------------------------------------------------------
// softmax + context v3: grid (16 d-chunks of 64, 32 b), 512 threads;
// 64 t-phases (tph = wid*4 + lane>>3), 8 uint4 lanes per chunk
// ---------------------------------------------------------------
__global__ void __launch_bounds__(512) ctx_kernel() {
    int b = blockIdx.y, tid = threadIdx.x;
    int lane = tid & 31, wid = tid >> 5;
    __shared__ float sal[512];
    __shared__ float racc[64 * 64];     // 16 KB: [phase][dlocal]
    __shared__ float part2[8 * 64];     // 2 KB
    __shared__ float wm[16], ws[16];

    float v = g_scores[(b << 9) + tid];
    float m = v;
#pragma unroll
    for (int o = 16; o; o >>= 1) m = fmaxf(m, __shfl_xor_sync(0xffffffffu, m, o));
    if (lane == 0) wm[wid] = m;
    __syncthreads();
    if (tid < 16) {
        float x = wm[tid];
#pragma unroll
        for (int o = 8; o; o >>= 1) x = fmaxf(x, __shfl_xor_sync(0xffffu, x, o));
        wm[tid] = x;
    }
    __syncthreads();
    float mx = wm[0];
    float e = __expf(v - mx);
    sal[tid] = e;
    float s = e;
#pragma unroll
    for (int o = 16; o; o >>= 1) s += __shfl_xor_sync(0xffffffffu, s, o);
    if (lane == 0) ws[wid] = s;
    __syncthreads();
    if (tid < 16) {
        float x = ws[tid];
#pragma unroll
        for (int o = 8; o; o >>= 1) x += __shfl_xor_sync(0xffffu, x, o);
        ws[tid] = x;
    }
    __syncthreads();
    float inv = __fdividef(1.0f, ws[0]);

    // 64 t-phases; each 1/4-warp (8 lanes) covers 64 d = 8 uint4
    int tph = (wid << 2) + (lane >> 3);     // 0..63
    int dl  = lane & 7;                      // uint4 slot within 64-d chunk
    const uint4* vp = (const uint4*)g_val + ((size_t)b << 16) + (blockIdx.x << 3) + dl;
    float a0=0,a1=0,a2=0,a3=0,a4=0,a5=0,a6=0,a7=0;
#pragma unroll
    for (int t = tph; t < 512; t += 64) {
        uint4 vv = __ldg(vp + ((size_t)t << 7));
        float sc = sal[t];
        const __half2* hp = (const __half2*)&vv;
        float2 f0 = __half22float2(hp[0]);
        float2 f1 = __half22float2(hp[1]);
        float2 f2 = __half22float2(hp[2]);
        float2 f3 = __half22float2(hp[3]);
        a0 += sc * f0.x; a1 += sc * f0.y; a2 += sc * f1.x; a3 += sc * f1.y;
        a4 += sc * f2.x; a5 += sc * f2.y; a6 += sc * f3.x; a7 += sc * f3.y;
    }
    float4* r4 = (float4*)racc;
    int base4 = (tph << 4) + (dl << 1);     // (tph*64 + dl*8)/4
    r4[base4]     = make_float4(a0, a1, a2, a3);
    r4[base4 + 1] = make_float4(a4, a5, a6, a7);
    __syncthreads();

    // stage 2: 8 groups x 64 d (each sums 8 phases)
    {
        int d = tid & 63, g = tid >> 6;
        float sum = 0.f;
#pragma unroll
        for (int i = 0; i < 8; i++) sum += racc[((g + (i << 3)) << 6) + d];
        part2[(g << 6) + d] = sum;
    }
    __syncthreads();
    if (tid < 64) {
        float sum = 0.f;
#pragma unroll
        for (int g = 0; g < 8; g++) sum += part2[(g << 6) + tid];
        int k = 128 + (blockIdx.x << 6) + tid;   // x-vector index
        g_xT[((k >> 2) << 7) + (b << 2) + (k & 3)] = sum * inv;
    }
}

// ---------------------------------------------------------------
// lstm0 (R12 frozen): grid 512 (unit u), 256 threads (8 warps split k)
// ---------------------------------------------------------------
__global__ void __launch_bounds__(256) lstm0_kernel(const float* __restrict__ bih,
                                                    const float* __restrict__ bhh,
                                                    int p) {
    __shared__ float part[4][8][32];
    int u = blockIdx.x, w = threadIdx.x >> 5, lane = threadIdx.x & 31;
    const float4* xT4 = (const float4*)g_xT;
    const float4* hT4 = (const float4*)g_h0T[p];
    const uint2* wihv = (const uint2*)g_wih0h;
    const uint2* whhv = (const uint2*)g_whh0h;
    float acc[4] = {0.f, 0.f, 0.f, 0.f};

    for (int g = w * 36; g < w * 36 + 36; g++) {
        float4 xv = xT4[(g << 5) + lane];
#pragma unroll
        for (int gate = 0; gate < 4; gate++)
            acc[gate] += dot4h(__ldg(&wihv[(size_t)(gate * 512 + u) * 288 + g]), xv);
    }
    for (int g = w * 16; g < w * 16 + 16; g++) {
        float4 hv = hT4[(g << 5) + lane];
#pragma unroll
        for (int gate = 0; gate < 4; gate++)
            acc[gate] += dot4h(__ldg(&whhv[(size_t)(gate * 512 + u) * 128 + g]), hv);
    }
#pragma unroll
    for (int gate = 0; gate < 4; gate++) part[gate][w][lane] = acc[gate];
    __syncthreads();
    if (w == 0) {
        float gv[4];
#pragma unroll
        for (int gate = 0; gate < 4; gate++) {
            int j = gate * 512 + u;
            float s = 0.f;
#pragma unroll
            for (int i = 0; i < 8; i++) s += part[gate][i][lane];
            gv[gate] = s + bih[j] + bhh[j];
        }
        float c = g_c0[u * 32 + lane];
        float cn = sigm(gv[1]) * c + sigm(gv[0]) * fast_tanh(gv[2]);
        float hn = sigm(gv[3]) * fast_tanh(cn);
        g_c0[u * 32 + lane] = cn;
        g_h0T[1 - p][idx4(u, lane)] = hn;
    }
}

// ---------------------------------------------------------------
// lstm1 (+ q-projection) (R12 frozen): blocks<512 lstm, >=512 qproj
// ---------------------------------------------------------------
__global__ void __launch_bounds__(256) lstm1q_kernel(const float* __restrict__ bih,
                                                     const float* __restrict__ bhh,
                                                     int p) {
    int w = threadIdx.x >> 5, lane = threadIdx.x & 31;
    const float4* h0n = (const float4*)g_h0T[1 - p];
    if (blockIdx.x < 512) {
        __shared__ float part[4][8][32];
        int u = blockIdx.x;
        const float4* hT4 = (const float4*)g_h1T[p];
        const uint2* wihv = (const uint2*)g_wih1h;
        const uint2* whhv = (const uint2*)g_whh1h;
        float acc[4] = {0.f, 0.f, 0.f, 0.f};
        for (int g = w * 16; g < w * 16 + 16; g++) {
            float4 xv = h0n[(g << 5) + lane];
            float4 hv = hT4[(g << 5) + lane];
#pragma unroll
            for (int gate = 0; gate < 4; gate++) {
                int j = gate * 512 + u;
                acc[gate] += dot4h(__ldg(&wihv[(size_t)j * 128 + g]), xv);
                acc[gate] += dot4h(__ldg(&whhv[(size_t)j * 128 + g]), hv);
            }
        }
#pragma unroll
        for (int gate = 0; gate < 4; gate++) part[gate][w][lane] = acc[gate];
        __syncthreads();
        if (w == 0) {
            float gv[4];
#pragma unroll
            for (int gate = 0; gate < 4; gate++) {
                int j = gate * 512 + u;
                float s = 0.f;
#pragma unroll
                for (int i = 0; i < 8; i++) s += part[gate][i][lane];
                gv[gate] = s + bih[j] + bhh[j];
            }
            float c = g_c1[u * 32 + lane];
            float cn = sigm(gv[1]) * c + sigm(gv[0]) * fast_tanh(gv[2]);
            float hn = sigm(gv[3]) * fast_tanh(cn);
            g_c1[u * 32 + lane] = cn;
            g_h1T[1 - p][idx4(u, lane)] = hn;
        }
    } else {
        // q projection: q = h0n @ Wq^T (fp16 Wq), one warp per output feature j
        int j = (blockIdx.x - 512) * 8 + w;
        const uint2* wq = (const uint2*)(g_wqh + (size_t)j * 512);
        float acc = 0.f;
        for (int g = 0; g < 128; g++)
            acc += dot4h(__ldg(&wq[g]), h0n[(g << 5) + lane]);
        g_q[lane * 1024 + j] = acc;
    }
}

// ---------------------------------------------------------------
// fused fc (this step) + scores (next step)  (R12 frozen)
// ---------------------------------------------------------------
__global__ void __launch_bounds__(256) fcscores_kernel(const float* __restrict__ fc_w,
                                                       const float* __restrict__ fc_b,
                                                       const float* __restrict__ We,
                                                       float* __restrict__ out, int s, int p) {
    __shared__ float sq[1024], swe[1024];
    if (blockIdx.x < 16) {
        int w = threadIdx.x >> 5, lane = threadIdx.x & 31;
        int o = blockIdx.x * 8 + w;
        const float4* h1n = (const float4*)g_h1T[1 - p];
        const float4* fw = (const float4*)(fc_w + (size_t)o * 512);
        float acc = 0.f;
        for (int g = 0; g < 128; g++)
            acc += dot4(__ldg(&fw[g]), h1n[(g << 5) + lane]);
        float y = fmaxf(acc + fc_b[o], 0.f);
        out[(size_t)lane * (SDEC * OUTD) + s * OUTD + o] = y;
        g_xT[idx4(o, lane)] = 1.0f + y;
    } else {
        int idx = blockIdx.x - 16;
        scores_body(We, idx & 15, idx >> 4, threadIdx.x, sq, swe);
    }
}

// ---------------------------------------------------------------
extern "C" void kernel_launch(void* const* d_in, const int* in_sizes, int n_in,
                              void* d_out, int out_size) {
    const float* enc  = (const float*)d_in[0];
    const float* h0   = (const float*)d_in[1];
    const float* c0   = (const float*)d_in[2];
    const float* Wk   = (const float*)d_in[3];
    const float* Wq   = (const float*)d_in[4];
    const float* Wv   = (const float*)d_in[5];
    const float* We   = (const float*)d_in[6];
    const float* wih0 = (const float*)d_in[7];
    const float* whh0 = (const float*)d_in[8];
    const float* bih0 = (const float*)d_in[9];
    const float* bhh0 = (const float*)d_in[10];
    const float* wih1 = (const float*)d_in[11];
    const float* whh1 = (const float*)d_in[12];
    const float* bih1 = (const float*)d_in[13];
    const float* bhh1 = (const float*)d_in[14];
    const float* fc_w = (const float*)d_in[15];
    const float* fc_b = (const float*)d_in[16];
    float* out = (float*)d_out;

    convertw_kernel<<<368, 256>>>(wih0, whh0, wih1, whh1, Wq);
    init_kernel<<<40, 256>>>(h0, c0, Wq);
    gemm_kv_kernel<<<dim3(8, 128, 2), 256>>>(enc, Wk, Wv);
    // scores for step 0 (uses q from init)
    scores_kernel<<<dim3(16, 32), 256>>>(We);

    for (int s = 0; s < SDEC; s++) {
        int p = s & 1;
        ctx_kernel<<<dim3(16, 32), 512>>>();
        lstm0_kernel<<<512, 256>>>(bih0, bhh0, p);
        lstm1q_kernel<<<640, 256>>>(bih1, bhh1, p);
        // fc for this step + scores for next step (last iteration's scores unused)
        fcscores_kernel<<<528, 256>>>(fc_w, fc_b, We, out, s, p);
    }
}

// round 17
// speedup vs baseline: 1.6587x; 1.1003x over previous
#include <cuda_runtime.h>
#include <cuda_fp16.h>
#include <mma.h>

using namespace nvcuda;

#define BB   32
#define TT   512
#define HHD  512
#define KVD  1024
#define OUTD 128
#define XKD  1152   // OUT + KV
#define SDEC 128

// ---------------- static scratch ----------------
__device__ __half g_key[BB*TT*KVD];           // 33.5 MB (fp16)
__device__ __half g_val[BB*TT*KVD];           // 33.5 MB (fp16)
__device__ alignas(16) __half g_wih0h[2048*XKD];
__device__ alignas(16) __half g_whh0h[2048*HHD];
__device__ alignas(16) __half g_wih1h[2048*HHD];
__device__ alignas(16) __half g_whh1h[2048*HHD];
__device__ alignas(16) __half g_wqh[KVD*HHD];
__device__ float g_q[BB*KVD];
__device__ float g_scores[BB*TT];
__device__ float g_xT[(XKD/4)*BB*4];          // x=[y,ctx] grouped-4 transposed
__device__ float g_h0T[2][(HHD/4)*BB*4];      // ping-pong
__device__ float g_h1T[2][(HHD/4)*BB*4];
__device__ float g_c0[HHD*BB];                // [u][b]
__device__ float g_c1[HHD*BB];

__device__ __forceinline__ float fast_tanh(float x) {      // accurate (LSTM cells)
    float e = __expf(2.0f * x);
    return 1.0f - __fdividef(2.0f, e + 1.0f);
}
__device__ __forceinline__ float tanha(float x) {          // HW MUFU (scores)
    float y; asm("tanh.approx.f32 %0, %1;" : "=f"(y) : "f"(x)); return y;
}
__device__ __forceinline__ float sigm(float x) {
    return __fdividef(1.0f, 1.0f + __expf(-x));
}
__device__ __forceinline__ float dot4(float4 a, float4 b) {
    return a.x*b.x + a.y*b.y + a.z*b.z + a.w*b.w;
}
// dot of 4 halves (packed in uint2) with float4
__device__ __forceinline__ float dot4h(uint2 wv, float4 x) {
    __half2* hp = (__half2*)&wv;
    float2 a = __half22float2(hp[0]);
    float2 b = __half22float2(hp[1]);
    return a.x * x.x + a.y * x.y + b.x * x.z + b.y * x.w;
}
// grouped-4 transposed float index for (k, batch m)
__device__ __forceinline__ int idx4(int k, int m) { return ((k >> 2) << 7) + (m << 2) + (k & 3); }

// ---------------------------------------------------------------
// convert weights to fp16 (one-time): 16384 floats per block
// ---------------------------------------------------------------
__global__ void __launch_bounds__(256) convertw_kernel(const float* __restrict__ wih0,
                                                       const float* __restrict__ whh0,
                                                       const float* __restrict__ wih1,
                                                       const float* __restrict__ whh1,
                                                       const float* __restrict__ Wq) {
    int bx = blockIdx.x;
    const float* src; __half* dst; size_t off;
    if (bx < 144)      { src = wih0; dst = g_wih0h; off = (size_t)bx * 16384; }
    else if (bx < 208) { src = whh0; dst = g_whh0h; off = (size_t)(bx - 144) * 16384; }
    else if (bx < 272) { src = wih1; dst = g_wih1h; off = (size_t)(bx - 208) * 16384; }
    else if (bx < 336) { src = whh1; dst = g_whh1h; off = (size_t)(bx - 272) * 16384; }
    else               { src = Wq;   dst = g_wqh;   off = (size_t)(bx - 336) * 16384; }
    const float4* s4 = (const float4*)(src + off);
    for (int i = threadIdx.x; i < 4096; i += 256) {
        float4 v = __ldg(s4 + i);
        union { __half h[4]; uint2 u; } pk;
        pk.h[0] = __float2half_rn(v.x); pk.h[1] = __float2half_rn(v.y);
        pk.h[2] = __float2half_rn(v.z); pk.h[3] = __float2half_rn(v.w);
        *(uint2*)(dst + off + (size_t)i * 4) = pk.u;
    }
}

// ---------------------------------------------------------------
// init: blocks 0..31 -> q0 = h0[0] @ Wq^T ; blocks 32..39 -> state transpose + y0=0
// ---------------------------------------------------------------
__global__ void init_kernel(const float* __restrict__ h0, const float* __restrict__ c0,
                            const float* __restrict__ Wq) {
    int bx = blockIdx.x, tid = threadIdx.x;
    if (bx < 32) {
        __shared__ float sh[512];
        for (int p = tid; p < 512; p += 256) sh[p] = h0[bx * 512 + p];
        __syncthreads();
        int w = tid >> 5, lane = tid & 31;
        const float4* shv = (const float4*)sh;
        for (int jj = 0; jj < 128; jj++) {
            int j = (w << 7) + jj;
            const float4* wq = (const float4*)(Wq + (size_t)j * 512);
            float acc = 0.f;
#pragma unroll
            for (int i = 0; i < 4; i++)
                acc += dot4(__ldg(&wq[lane + (i << 5)]), shv[lane + (i << 5)]);
#pragma unroll
            for (int off = 16; off; off >>= 1) acc += __shfl_xor_sync(0xffffffffu, acc, off);
            if (lane == 0) g_q[(bx << 10) + j] = acc;
        }
    } else {
        int p0 = (bx - 32) * 256 + tid;
        for (int i = p0; i < BB * HHD; i += 8 * 256) {
            int b = i >> 9, u = i & 511;
            int ix = idx4(u, b);
            g_h0T[0][ix] = h0[i];
            g_h1T[0][ix] = h0[BB * HHD + i];
            g_c0[u * 32 + b] = c0[i];
            g_c1[u * 32 + b] = c0[BB * HHD + i];
        }
        for (int i = p0; i < OUTD * 32; i += 8 * 256) g_xT[i] = 0.f;
    }
}

// ---------------------------------------------------------------
// key/value precompute via WMMA, double-buffered software pipeline
// ---------------------------------------------------------------
__global__ void __launch_bounds__(256) gemm_kv_kernel(const float* __restrict__ A,
                                                      const float* __restrict__ Wk,
                                                      const float* __restrict__ Wv) {
    const float* W = blockIdx.z ? Wv : Wk;
    __half* C = blockIdx.z ? g_val : g_key;
    int m0 = blockIdx.y << 7, n0 = blockIdx.x << 7;
    __shared__ alignas(256) __half As[2][128][40];
    __shared__ alignas(256) __half Bs[2][128][40];
    __shared__ alignas(256) float stage[8][256];
    int tid = threadIdx.x, lane = tid & 31, wid = tid >> 5;
    int wm = (wid & 3) << 5;
    int wn = (wid >> 2) << 6;

    wmma::fragment<wmma::accumulator, 16, 16, 16, float> acc[2][4];
#pragma unroll
    for (int mf = 0; mf < 2; mf++)
#pragma unroll
        for (int nf = 0; nf < 4; nf++) wmma::fill_fragment(acc[mf][nf], 0.0f);

    int r = tid & 127;
    const float* srcrow = (tid < 128) ? (A + (size_t)(m0 + r) * 1024)
                                      : (W + (size_t)(n0 + r) * 1024);

    float4 f[8];
#define GEMM_LOAD(k0)                                                   \
    {                                                                   \
        _Pragma("unroll")                                               \
        for (int j = 0; j < 4; j++) {                                   \
            f[2*j]   = __ldg((const float4*)(srcrow + (k0) + j * 8));   \
            f[2*j+1] = __ldg((const float4*)(srcrow + (k0) + j * 8 + 4));\
        }                                                               \
    }
#define GEMM_STORE(buf)                                                 \
    {                                                                   \
        __half* dstrow = (tid < 128) ? &As[buf][r][0] : &Bs[buf][r][0]; \
        _Pragma("unroll")                                               \
        for (int j = 0; j < 4; j++) {                                   \
            union { __half h[8]; uint4 u; } pk;                         \
            pk.h[0] = __float2half_rn(f[2*j].x);                        \
            pk.h[1] = __float2half_rn(f[2*j].y);                        \
            pk.h[2] = __float2half_rn(f[2*j].z);                        \
            pk.h[3] = __float2half_rn(f[2*j].w);                        \
            pk.h[4] = __float2half_rn(f[2*j+1].x);                      \
            pk.h[5] = __float2half_rn(f[2*j+1].y);                      \
            pk.h[6] = __float2half_rn(f[2*j+1].z);                      \
            pk.h[7] = __float2half_rn(f[2*j+1].w);                      \
            *(uint4*)(dstrow + j * 8) = pk.u;                           \
        }                                                               \
    }

    GEMM_LOAD(0);
    GEMM_STORE(0);
    __syncthreads();

    for (int c = 0; c < 32; c++) {
        if (c < 31) GEMM_LOAD((c + 1) << 5);
        int buf = c & 1;
#pragma unroll
        for (int ks = 0; ks < 32; ks += 16) {
            wmma::fragment<wmma::matrix_a, 16, 16, 16, __half, wmma::row_major> af[2];
            wmma::fragment<wmma::matrix_b, 16, 16, 16, __half, wmma::col_major> bf[4];
#pragma unroll
            for (int mf = 0; mf < 2; mf++)
                wmma::load_matrix_sync(af[mf], &As[buf][wm + (mf << 4)][ks], 40);
#pragma unroll
            for (int nf = 0; nf < 4; nf++)
                wmma::load_matrix_sync(bf[nf], &Bs[buf][wn + (nf << 4)][ks], 40);
#pragma unroll
            for (int mf = 0; mf < 2; mf++)
#pragma unroll
                for (int nf = 0; nf < 4; nf++)
                    wmma::mma_sync(acc[mf][nf], af[mf], bf[nf], acc[mf][nf]);
        }
        if (c < 31) GEMM_STORE((c + 1) & 1);
        __syncthreads();
    }
#undef GEMM_LOAD
#undef GEMM_STORE

#pragma unroll
    for (int mf = 0; mf < 2; mf++)
#pragma unroll
        for (int nf = 0; nf < 4; nf++) {
            wmma::store_matrix_sync(stage[wid], acc[mf][nf], 16, wmma::mem_row_major);
            __syncwarp();
#pragma unroll
            for (int i = lane; i < 128; i += 32) {
                int rr = i >> 3, c2 = (i & 7) << 1;
                __half2 h = __floats2half2_rn(stage[wid][rr * 16 + c2],
                                              stage[wid][rr * 16 + c2 + 1]);
                *(__half2*)(C + (size_t)(m0 + wm + (mf << 4) + rr) * 1024
                              + n0 + wn + (nf << 4) + c2) = h;
            }
            __syncwarp();
        }
}

// ---------------------------------------------------------------
// scores body v2 (register-resident q/We, no smem, no syncthreads):
// 256 threads; (chunk, b) = 32-t slab; warp owns 4 rows
// ---------------------------------------------------------------
__device__ __forceinline__ void scores_body(const float* __restrict__ We,
                                            int chunk, int b, int tid) {
    int w = tid >> 5, lane = tid & 31;
    const float4* qg = (const float4*)(g_q + (b << 10));
    const float4* wg = (const float4*)We;
    float4 qr[8], wr[8];
#pragma unroll
    for (int i = 0; i < 4; i++) {
        int q4 = (lane + (i << 5)) << 1;
        qr[2*i]   = __ldg(&qg[q4]);
        qr[2*i+1] = __ldg(&qg[q4 + 1]);
        wr[2*i]   = __ldg(&wg[q4]);
        wr[2*i+1] = __ldg(&wg[q4 + 1]);
    }
#pragma unroll
    for (int r = 0; r < 4; r++) {
        int t = (chunk << 5) + (w << 2) + r;
        const uint4* kp = (const uint4*)(g_key + ((size_t)(b * 512 + t) << 10));
        uint4 kk[4];
#pragma unroll
        for (int i = 0; i < 4; i++) kk[i] = __ldg(&kp[lane + (i << 5)]);
        float acc = 0.f;
#pragma unroll
        for (int i = 0; i < 4; i++) {
            float4 qa = qr[2*i], qb = qr[2*i+1];
            float4 wa = wr[2*i], wb = wr[2*i+1];
            const __half2* hp = (const __half2*)&kk[i];
            float2 f0 = __half22float2(hp[0]);
            float2 f1 = __half22float2(hp[1]);
            float2 f2 = __half22float2(hp[2]);
            float2 f3 = __half22float2(hp[3]);
            acc += wa.x * tanha(qa.x + f0.x);
            acc += wa.y * tanha(qa.y + f0.y);
            acc += wa.z * tanha(qa.z + f1.x);
            acc += wa.w * tanha(qa.w + f1.y);
            acc += wb.x * tanha(qb.x + f2.x);
            acc += wb.y * tanha(qb.y + f2.y);
            acc += wb.z * tanha(qb.z + f3.x);
            acc += wb.w * tanha(qb.w + f3.y);
        }
#pragma unroll
        for (int off = 16; off; off >>= 1) acc += __shfl_xor_sync(0xffffffffu, acc, off);
        if (lane == 0) g_scores[(b << 9) + t] = acc;
    }
}

__global__ void __launch_bounds__(256) scores_kernel(const float* __restrict__ We) {
    scores_body(We, blockIdx.x, blockIdx.y, threadIdx.x);
}

// ---------------------------------------------------------------
// softmax + context v3: grid (16 d-chunks of 64, 32 b), 512 threads;
// 64 t-phases (tph = wid*4 + lane>>3), 8 uint4 lanes per chunk
// ---------------------------------------------------------------
__global__ void __launch_bounds__(512) ctx_kernel() {
    int b = blockIdx.y, tid = threadIdx.x;
    int lane = tid & 31, wid = tid >> 5;
    __shared__ float sal[512];
    __shared__ float racc[64 * 64];     // 16 KB: [phase][dlocal]
    __shared__ float part2[8 * 64];     // 2 KB
    __shared__ float wm[16], ws[16];

    float v = g_scores[(b << 9) + tid];
    float m = v;
#pragma unroll
    for (int o = 16; o; o >>= 1) m = fmaxf(m, __shfl_xor_sync(0xffffffffu, m, o));
    if (lane == 0) wm[wid] = m;
    __syncthreads();
    if (tid < 16) {
        float x = wm[tid];
#pragma unroll
        for (int o = 8; o; o >>= 1) x = fmaxf(x, __shfl_xor_sync(0xffffu, x, o));
        wm[tid] = x;
    }
    __syncthreads();
    float mx = wm[0];
    float e = __expf(v - mx);
    sal[tid] = e;
    float s = e;
#pragma unroll
    for (int o = 16; o; o >>= 1) s += __shfl_xor_sync(0xffffffffu, s, o);
    if (lane == 0) ws[wid] = s;
    __syncthreads();
    if (tid < 16) {
        float x = ws[tid];
#pragma unroll
        for (int o = 8; o; o >>= 1) x += __shfl_xor_sync(0xffffu, x, o);
        ws[tid] = x;
    }
    __syncthreads();
    float inv = __fdividef(1.0f, ws[0]);

    // 64 t-phases; each 1/4-warp (8 lanes) covers 64 d = 8 uint4
    int tph = (wid << 2) + (lane >> 3);     // 0..63
    int dl  = lane & 7;                      // uint4 slot within 64-d chunk
    const uint4* vp = (const uint4*)g_val + ((size_t)b << 16) + (blockIdx.x << 3) + dl;
    float a0=0,a1=0,a2=0,a3=0,a4=0,a5=0,a6=0,a7=0;
#pragma unroll
    for (int t = tph; t < 512; t += 64) {
        uint4 vv = __ldg(vp + ((size_t)t << 7));
        float sc = sal[t];
        const __half2* hp = (const __half2*)&vv;
        float2 f0 = __half22float2(hp[0]);
        float2 f1 = __half22float2(hp[1]);
        float2 f2 = __half22float2(hp[2]);
        float2 f3 = __half22float2(hp[3]);
        a0 += sc * f0.x; a1 += sc * f0.y; a2 += sc * f1.x; a3 += sc * f1.y;
        a4 += sc * f2.x; a5 += sc * f2.y; a6 += sc * f3.x; a7 += sc * f3.y;
    }
    float4* r4 = (float4*)racc;
    int base4 = (tph << 4) + (dl << 1);     // (tph*64 + dl*8)/4
    r4[base4]     = make_float4(a0, a1, a2, a3);
    r4[base4 + 1] = make_float4(a4, a5, a6, a7);
    __syncthreads();

    // stage 2: 8 groups x 64 d (each sums 8 phases)
    {
        int d = tid & 63, g = tid >> 6;
        float sum = 0.f;
#pragma unroll
        for (int i = 0; i < 8; i++) sum += racc[((g + (i << 3)) << 6) + d];
        part2[(g << 6) + d] = sum;
    }
    __syncthreads();
    if (tid < 64) {
        float sum = 0.f;
#pragma unroll
        for (int g = 0; g < 8; g++) sum += part2[(g << 6) + tid];
        int k = 128 + (blockIdx.x << 6) + tid;   // x-vector index
        g_xT[((k >> 2) << 7) + (b << 2) + (k & 3)] = sum * inv;
    }
}

// ---------------------------------------------------------------
// lstm0 (R12 frozen): grid 512 (unit u), 256 threads (8 warps split k)
// ---------------------------------------------------------------
__global__ void __launch_bounds__(256) lstm0_kernel(const float* __restrict__ bih,
                                                    const float* __restrict__ bhh,
                                                    int p) {
    __shared__ float part[4][8][32];
    int u = blockIdx.x, w = threadIdx.x >> 5, lane = threadIdx.x & 31;
    const float4* xT4 = (const float4*)g_xT;
    const float4* hT4 = (const float4*)g_h0T[p];
    const uint2* wihv = (const uint2*)g_wih0h;
    const uint2* whhv = (const uint2*)g_whh0h;
    float acc[4] = {0.f, 0.f, 0.f, 0.f};

    for (int g = w * 36; g < w * 36 + 36; g++) {
        float4 xv = xT4[(g << 5) + lane];
#pragma unroll
        for (int gate = 0; gate < 4; gate++)
            acc[gate] += dot4h(__ldg(&wihv[(size_t)(gate * 512 + u) * 288 + g]), xv);
    }
    for (int g = w * 16; g < w * 16 + 16; g++) {
        float4 hv = hT4[(g << 5) + lane];
#pragma unroll
        for (int gate = 0; gate < 4; gate++)
            acc[gate] += dot4h(__ldg(&whhv[(size_t)(gate * 512 + u) * 128 + g]), hv);
    }
#pragma unroll
    for (int gate = 0; gate < 4; gate++) part[gate][w][lane] = acc[gate];
    __syncthreads();
    if (w == 0) {
        float gv[4];
#pragma unroll
        for (int gate = 0; gate < 4; gate++) {
            int j = gate * 512 + u;
            float s = 0.f;
#pragma unroll
            for (int i = 0; i < 8; i++) s += part[gate][i][lane];
            gv[gate] = s + bih[j] + bhh[j];
        }
        float c = g_c0[u * 32 + lane];
        float cn = sigm(gv[1]) * c + sigm(gv[0]) * fast_tanh(gv[2]);
        float hn = sigm(gv[3]) * fast_tanh(cn);
        g_c0[u * 32 + lane] = cn;
        g_h0T[1 - p][idx4(u, lane)] = hn;
    }
}

// ---------------------------------------------------------------
// lstm1 (+ q-projection) (R12 frozen): blocks<512 lstm, >=512 qproj
// ---------------------------------------------------------------
__global__ void __launch_bounds__(256) lstm1q_kernel(const float* __restrict__ bih,
                                                     const float* __restrict__ bhh,
                                                     int p) {
    int w = threadIdx.x >> 5, lane = threadIdx.x & 31;
    const float4* h0n = (const float4*)g_h0T[1 - p];
    if (blockIdx.x < 512) {
        __shared__ float part[4][8][32];
        int u = blockIdx.x;
        const float4* hT4 = (const float4*)g_h1T[p];
        const uint2* wihv = (const uint2*)g_wih1h;
        const uint2* whhv = (const uint2*)g_whh1h;
        float acc[4] = {0.f, 0.f, 0.f, 0.f};
        for (int g = w * 16; g < w * 16 + 16; g++) {
            float4 xv = h0n[(g << 5) + lane];
            float4 hv = hT4[(g << 5) + lane];
#pragma unroll
            for (int gate = 0; gate < 4; gate++) {
                int j = gate * 512 + u;
                acc[gate] += dot4h(__ldg(&wihv[(size_t)j * 128 + g]), xv);
                acc[gate] += dot4h(__ldg(&whhv[(size_t)j * 128 + g]), hv);
            }
        }
#pragma unroll
        for (int gate = 0; gate < 4; gate++) part[gate][w][lane] = acc[gate];
        __syncthreads();
        if (w == 0) {
            float gv[4];
#pragma unroll
            for (int gate = 0; gate < 4; gate++) {
                int j = gate * 512 + u;
                float s = 0.f;
#pragma unroll
                for (int i = 0; i < 8; i++) s += part[gate][i][lane];
                gv[gate] = s + bih[j] + bhh[j];
            }
            float c = g_c1[u * 32 + lane];
            float cn = sigm(gv[1]) * c + sigm(gv[0]) * fast_tanh(gv[2]);
            float hn = sigm(gv[3]) * fast_tanh(cn);
            g_c1[u * 32 + lane] = cn;
            g_h1T[1 - p][idx4(u, lane)] = hn;
        }
    } else {
        // q projection: q = h0n @ Wq^T (fp16 Wq), one warp per output feature j
        int j = (blockIdx.x - 512) * 8 + w;
        const uint2* wq = (const uint2*)(g_wqh + (size_t)j * 512);
        float acc = 0.f;
        for (int g = 0; g < 128; g++)
            acc += dot4h(__ldg(&wq[g]), h0n[(g << 5) + lane]);
        g_q[lane * 1024 + j] = acc;
    }
}

// ---------------------------------------------------------------
// fused fc (this step) + scores (next step)
// ---------------------------------------------------------------
__global__ void __launch_bounds__(256) fcscores_kernel(const float* __restrict__ fc_w,
                                                       const float* __restrict__ fc_b,
                                                       const float* __restrict__ We,
                                                       float* __restrict__ out, int s, int p) {
    if (blockIdx.x < 16) {
        int w = threadIdx.x >> 5, lane = threadIdx.x & 31;
        int o = blockIdx.x * 8 + w;
        const float4* h1n = (const float4*)g_h1T[1 - p];
        const float4* fw = (const float4*)(fc_w + (size_t)o * 512);
        float acc = 0.f;
        for (int g = 0; g < 128; g++)
            acc += dot4(__ldg(&fw[g]), h1n[(g << 5) + lane]);
        float y = fmaxf(acc + fc_b[o], 0.f);
        out[(size_t)lane * (SDEC * OUTD) + s * OUTD + o] = y;
        g_xT[idx4(o, lane)] = 1.0f + y;
    } else {
        int idx = blockIdx.x - 16;
        scores_body(We, idx & 15, idx >> 4, threadIdx.x);
    }
}

// ---------------------------------------------------------------
extern "C" void kernel_launch(void* const* d_in, const int* in_sizes, int n_in,
                              void* d_out, int out_size) {
    const float* enc  = (const float*)d_in[0];
    const float* h0   = (const float*)d_in[1];
    const float* c0   = (const float*)d_in[2];
    const float* Wk   = (const float*)d_in[3];
    const float* Wq   = (const float*)d_in[4];
    const float* Wv   = (const float*)d_in[5];
    const float* We   = (const float*)d_in[6];
    const float* wih0 = (const float*)d_in[7];
    const float* whh0 = (const float*)d_in[8];
    const float* bih0 = (const float*)d_in[9];
    const float* bhh0 = (const float*)d_in[10];
    const float* wih1 = (const float*)d_in[11];
    const float* whh1 = (const float*)d_in[12];
    const float* bih1 = (const float*)d_in[13];
    const float* bhh1 = (const float*)d_in[14];
    const float* fc_w = (const float*)d_in[15];
    const float* fc_b = (const float*)d_in[16];
    float* out = (float*)d_out;

    convertw_kernel<<<368, 256>>>(wih0, whh0, wih1, whh1, Wq);
    init_kernel<<<40, 256>>>(h0, c0, Wq);
    gemm_kv_kernel<<<dim3(8, 128, 2), 256>>>(enc, Wk, Wv);
    // scores for step 0 (uses q from init)
    scores_kernel<<<dim3(16, 32), 256>>>(We);

    for (int s = 0; s < SDEC; s++) {
        int p = s & 1;
        ctx_kernel<<<dim3(16, 32), 512>>>();
        lstm0_kernel<<<512, 256>>>(bih0, bhh0, p);
        lstm1q_kernel<<<640, 256>>>(bih1, bhh1, p);
        // fc for this step + scores for next step (last iteration's scores unused)
        fcscores_kernel<<<528, 256>>>(fc_w, fc_b, We, out, s, p);
    }
}